// round 13
// baseline (speedup 1.0000x reference)
#include <cuda_runtime.h>
#include <cuda_bf16.h>
#include <cstdint>

// Problem shape (fixed by dataset)
#define B_ROWS 1024
#define C_COLS 32768
#define D_DIM  512

// GEMM tiling: CTA 128x256, 8 warps, warp tile 64x64, reg-heavy (1 CTA/SM)
#define BM 128
#define BN 256
#define BK 64
#define SA 72            // padded smem row stride (bf16): 144 B, 16B-aligned rows, ldmatrix conflict-free
#define NK (D_DIM / BK)  // 8
#define NSTAGE 3

#define A_SZ (BM * SA * 2)              // 18432 B per stage
#define B_SZ (BN * SA * 2)              // 36864 B per stage
#define STAGE (A_SZ + B_SZ)             // 55296 B
#define RED_OFF (NSTAGE * STAGE)        // 165888
#define SMEM_TOTAL (RED_OFF + BM * 4)   // +red[BM] = 166400 B

// Scratch (static device globals: allocation-free per harness rules).
__device__ __align__(16) __nv_bfloat16 g_Bn[(size_t)B_ROWS * D_DIM];
__device__ __align__(16) __nv_bfloat16 g_Pn[(size_t)C_COLS * D_DIM];
__device__ float g_rowacc[B_ROWS];
__device__ float g_pos[B_ROWS];

__device__ __forceinline__ uint32_t smem_u32(const void* p) {
    uint32_t a;
    asm("{ .reg .u64 t; cvta.to.shared.u64 t, %1; cvt.u32.u64 %0, t; }" : "=r"(a) : "l"(p));
    return a;
}
__device__ __forceinline__ void cp_async16(uint32_t sm, const void* gm) {
    asm volatile("cp.async.cg.shared.global [%0], [%1], 16;\n" ::"r"(sm), "l"(gm));
}
__device__ __forceinline__ void ldm_x4(uint32_t& r0, uint32_t& r1, uint32_t& r2, uint32_t& r3,
                                       uint32_t addr) {
    asm volatile("ldmatrix.sync.aligned.m8n8.x4.shared.b16 {%0,%1,%2,%3}, [%4];"
                 : "=r"(r0), "=r"(r1), "=r"(r2), "=r"(r3)
                 : "r"(addr));
}

// ---------------------------------------------------------------------------
// Normalize embeddings -> bf16 (norm 3), zero row accumulators
// ---------------------------------------------------------------------------
__global__ void k_norm_emb(const float* __restrict__ x) {
    int row = blockIdx.x;
    int tid = threadIdx.x;
    const float4* src = (const float4*)(x + (size_t)row * D_DIM);
    float4 v = src[tid];
    float s = v.x * v.x + v.y * v.y + v.z * v.z + v.w * v.w;
#pragma unroll
    for (int o = 16; o > 0; o >>= 1) s += __shfl_xor_sync(0xffffffffu, s, o);
    __shared__ float ss[4];
    if ((tid & 31) == 0) ss[tid >> 5] = s;
    __syncthreads();
    float tot = ss[0] + ss[1] + ss[2] + ss[3];
    float scale = 3.0f / fmaxf(sqrtf(tot), 1e-12f);
    __nv_bfloat162 p0 = __floats2bfloat162_rn(v.x * scale, v.y * scale);
    __nv_bfloat162 p1 = __floats2bfloat162_rn(v.z * scale, v.w * scale);
    __nv_bfloat162* dst = (__nv_bfloat162*)(g_Bn + (size_t)row * D_DIM + tid * 4);
    dst[0] = p0;
    dst[1] = p1;
    if (tid == 0) g_rowacc[row] = 0.0f;
}

// ---------------------------------------------------------------------------
// Normalize proxies -> bf16 (norm 3)
// ---------------------------------------------------------------------------
__global__ void k_norm_pxy(const float* __restrict__ x) {
    int row = blockIdx.x;
    int tid = threadIdx.x;
    const float4* src = (const float4*)(x + (size_t)row * D_DIM);
    float4 v = src[tid];
    float s = v.x * v.x + v.y * v.y + v.z * v.z + v.w * v.w;
#pragma unroll
    for (int o = 16; o > 0; o >>= 1) s += __shfl_xor_sync(0xffffffffu, s, o);
    __shared__ float ss[4];
    if ((tid & 31) == 0) ss[tid >> 5] = s;
    __syncthreads();
    float tot = ss[0] + ss[1] + ss[2] + ss[3];
    float scale = 3.0f / fmaxf(sqrtf(tot), 1e-12f);
    __nv_bfloat162 p0 = __floats2bfloat162_rn(v.x * scale, v.y * scale);
    __nv_bfloat162 p1 = __floats2bfloat162_rn(v.z * scale, v.w * scale);
    __nv_bfloat162* dst = (__nv_bfloat162*)(g_Pn + (size_t)row * D_DIM + tid * 4);
    dst[0] = p0;
    dst[1] = p1;
}

// ---------------------------------------------------------------------------
// Positive distances with labels dtype autodetect (int32 vs int64 storage)
// ---------------------------------------------------------------------------
__global__ void k_pos(const int* __restrict__ lab32) {
    int row = blockIdx.x;
    int tid = threadIdx.x;
    int det = 0;
    for (int j = tid; j < 512; j += 128) det |= lab32[2 * j + 1];
#pragma unroll
    for (int o = 16; o > 0; o >>= 1) det |= __shfl_xor_sync(0xffffffffu, det, o);
    __shared__ int sOr[4];
    if ((tid & 31) == 0) sOr[tid >> 5] = det;
    __syncthreads();
    int is64 = ((sOr[0] | sOr[1] | sOr[2] | sOr[3]) == 0);
    int lab = is64 ? lab32[2 * row] : lab32[row];
    lab &= (C_COLS - 1);

    const __nv_bfloat162* a = (const __nv_bfloat162*)(g_Bn + (size_t)row * D_DIM);
    const __nv_bfloat162* b = (const __nv_bfloat162*)(g_Pn + (size_t)lab * D_DIM);
    float s = 0.0f;
#pragma unroll
    for (int j = 0; j < 2; j++) {
        int idx = tid * 2 + j;
        float2 fa = __bfloat1622float2(a[idx]);
        float2 fb = __bfloat1622float2(b[idx]);
        s += fa.x * fb.x + fa.y * fb.y;
    }
#pragma unroll
    for (int o = 16; o > 0; o >>= 1) s += __shfl_xor_sync(0xffffffffu, s, o);
    __shared__ float ss[4];
    if ((tid & 31) == 0) ss[tid >> 5] = s;
    __syncthreads();
    if (tid == 0) {
        float dot = ss[0] + ss[1] + ss[2] + ss[3];
        g_pos[row] = 18.0f - 2.0f * dot;
    }
}

// ---------------------------------------------------------------------------
// GEMM s = Bn @ Pn^T fused with exp(2s-18) row-sum epilogue.
// grid = (C/BN, B/BM) = (128, 8), block = 256 (8 warps, 2x4 warp grid).
// Warp tile 64x64 (acc 128 regs). Fragments double-buffered across ks:
// ldmatrix for ks+1 issues before the 32 HMMAs of ks, hiding LDS latency.
// 3-stage cp.async pipeline, one barrier per k-iteration.
// ---------------------------------------------------------------------------
__global__ __launch_bounds__(256, 1) void k_gemm() {
    extern __shared__ __align__(16) char dsm[];
    float* red = (float*)(dsm + RED_OFF);

    int tid = threadIdx.x;
    int mBase = blockIdx.y * BM;
    int nBase = blockIdx.x * BN;
    int lane = tid & 31, warp = tid >> 5;
    int g = lane >> 2, t = lane & 3;
    int wm = (warp >> 2) * 64;  // 0 or 64
    int wn = (warp & 3) * 64;   // 0,64,128,192

    uint32_t sbase = smem_u32(dsm);

    // ldmatrix per-lane address components (conflict-free with SA=72)
    int aR = (lane & 7) + ((lane >> 3) & 1) * 8;
    int aC = ((lane >> 4) & 1) * 8;
    int bR = (lane & 7) + ((lane >> 4) & 1) * 8;
    int bC = ((lane >> 3) & 1) * 8;

    float acc[4][8][4];
#pragma unroll
    for (int mt = 0; mt < 4; mt++)
#pragma unroll
        for (int nt = 0; nt < 8; nt++)
#pragma unroll
            for (int cc = 0; cc < 4; cc++) acc[mt][nt][cc] = 0.0f;

    // double-buffered fragments
    uint32_t Af[2][4][4], Bf[2][8][2];

    int r = tid >> 3;        // 0..31
    int c8 = (tid & 7) * 8;  // 0..56 elems

    const __nv_bfloat16* gA0 = g_Bn + (size_t)mBase * D_DIM;
    const __nv_bfloat16* gB0 = g_Pn + (size_t)nBase * D_DIM;

    auto load_stage = [&](int kk) {
        uint32_t aB = sbase + (kk % NSTAGE) * STAGE;
        uint32_t bB = aB + A_SZ;
        int ko = kk * BK;
#pragma unroll
        for (int rr = r; rr < BM; rr += 32)
            cp_async16(aB + (rr * SA + c8) * 2, gA0 + (size_t)rr * D_DIM + ko + c8);
#pragma unroll
        for (int rr = r; rr < BN; rr += 32)
            cp_async16(bB + (rr * SA + c8) * 2, gB0 + (size_t)rr * D_DIM + ko + c8);
    };

    load_stage(0);
    asm volatile("cp.async.commit_group;\n");
    load_stage(1);
    asm volatile("cp.async.commit_group;\n");

    for (int kk = 0; kk < NK; kk++) {
        asm volatile("cp.async.wait_group 1;\n");  // stage kk resident
        __syncthreads();                           // visible to all; iter kk-1 reads done

        if (kk + 2 < NK) load_stage(kk + 2);       // overwrites stage read at iter kk-1
        asm volatile("cp.async.commit_group;\n");

        uint32_t aT = sbase + (kk % NSTAGE) * STAGE;
        uint32_t bT = aT + A_SZ;

        // fragment loader for one 16-wide K slice into buffer b
        auto ldfrags = [&](int ks, int b) {
            int kb = ks * 16;
#pragma unroll
            for (int mt = 0; mt < 4; mt++)
                ldm_x4(Af[b][mt][0], Af[b][mt][1], Af[b][mt][2], Af[b][mt][3],
                       aT + ((wm + mt * 16 + aR) * SA + kb + aC) * 2);
#pragma unroll
            for (int p = 0; p < 4; p++)
                ldm_x4(Bf[b][2 * p][0], Bf[b][2 * p][1], Bf[b][2 * p + 1][0],
                       Bf[b][2 * p + 1][1],
                       bT + ((wn + p * 16 + bR) * SA + kb + bC) * 2);
        };

        ldfrags(0, 0);  // one exposed preload per iteration
#pragma unroll
        for (int ks = 0; ks < 4; ks++) {
            int cb = ks & 1;
            if (ks < 3) ldfrags(ks + 1, cb ^ 1);  // prefetch next slice first
#pragma unroll
            for (int mt = 0; mt < 4; mt++)
#pragma unroll
                for (int nt = 0; nt < 8; nt++) {
                    asm volatile(
                        "mma.sync.aligned.m16n8k16.row.col.f32.bf16.bf16.f32 "
                        "{%0,%1,%2,%3}, {%4,%5,%6,%7}, {%8,%9}, {%0,%1,%2,%3};\n"
                        : "+f"(acc[mt][nt][0]), "+f"(acc[mt][nt][1]),
                          "+f"(acc[mt][nt][2]), "+f"(acc[mt][nt][3])
                        : "r"(Af[cb][mt][0]), "r"(Af[cb][mt][1]), "r"(Af[cb][mt][2]),
                          "r"(Af[cb][mt][3]), "r"(Bf[cb][nt][0]), "r"(Bf[cb][nt][1]));
                }
        }
    }

    // Epilogue: e = exp(2s - 18); per-row sums -> smem -> one global atomic/row
    __syncthreads();
    if (tid < BM) red[tid] = 0.0f;
    __syncthreads();

    float lsum[4][2];
#pragma unroll
    for (int mt = 0; mt < 4; mt++) { lsum[mt][0] = 0.0f; lsum[mt][1] = 0.0f; }
#pragma unroll
    for (int mt = 0; mt < 4; mt++)
#pragma unroll
        for (int nt = 0; nt < 8; nt++) {
            lsum[mt][0] += __expf(fmaf(2.0f, acc[mt][nt][0], -18.0f))
                         + __expf(fmaf(2.0f, acc[mt][nt][1], -18.0f));
            lsum[mt][1] += __expf(fmaf(2.0f, acc[mt][nt][2], -18.0f))
                         + __expf(fmaf(2.0f, acc[mt][nt][3], -18.0f));
        }
#pragma unroll
    for (int mt = 0; mt < 4; mt++)
#pragma unroll
        for (int h = 0; h < 2; h++) {
            float v = lsum[mt][h];
            v += __shfl_xor_sync(0xffffffffu, v, 1);
            v += __shfl_xor_sync(0xffffffffu, v, 2);
            if (t == 0) atomicAdd(&red[wm + mt * 16 + h * 8 + g], v);
        }
    __syncthreads();
    if (tid < BM) atomicAdd(&g_rowacc[mBase + tid], red[tid]);
}

// ---------------------------------------------------------------------------
// Finalize: loss_i = pos_dist_i + log(rowacc_i - exp(-pos_dist_i)); mean
// ---------------------------------------------------------------------------
__global__ void k_final(float* __restrict__ out) {
    int i = threadIdx.x;
    float pd = g_pos[i];
    float negsum = g_rowacc[i] - __expf(-pd);
    float v = pd + logf(negsum);
#pragma unroll
    for (int o = 16; o > 0; o >>= 1) v += __shfl_xor_sync(0xffffffffu, v, o);
    __shared__ float ss[32];
    if ((i & 31) == 0) ss[i >> 5] = v;
    __syncthreads();
    if (i < 32) {
        float w = ss[i];
#pragma unroll
        for (int o = 16; o > 0; o >>= 1) w += __shfl_xor_sync(0xffffffffu, w, o);
        if (i == 0) out[0] = w * (1.0f / (float)B_ROWS);
    }
}

// ---------------------------------------------------------------------------
extern "C" void kernel_launch(void* const* d_in, const int* in_sizes, int n_in,
                              void* d_out, int out_size) {
    (void)out_size;
    const float* emb = nullptr;
    const float* pxy = nullptr;
    const int* lab = nullptr;
    for (int i = 0; i < n_in; i++) {
        if (in_sizes[i] == B_ROWS * D_DIM) emb = (const float*)d_in[i];
        else if (in_sizes[i] == C_COLS * D_DIM) pxy = (const float*)d_in[i];
        else lab = (const int*)d_in[i];
    }
    float* out = (float*)d_out;

    static bool attr_done = false;
    if (!attr_done) {
        cudaFuncSetAttribute(k_gemm, cudaFuncAttributeMaxDynamicSharedMemorySize, SMEM_TOTAL);
        attr_done = true;
    }

    k_norm_emb<<<B_ROWS, 128>>>(emb);
    k_norm_pxy<<<C_COLS, 128>>>(pxy);
    k_pos<<<B_ROWS, 128>>>(lab);
    k_gemm<<<dim3(C_COLS / BN, B_ROWS / BM), 256, SMEM_TOTAL>>>();
    k_final<<<1, 1024>>>(out);
}

// round 14
// speedup vs baseline: 1.0681x; 1.0681x over previous
#include <cuda_runtime.h>
#include <cuda_bf16.h>
#include <cstdint>

// Problem shape (fixed by dataset)
#define B_ROWS 1024
#define C_COLS 32768
#define D_DIM  512

// GEMM tiling (R12 config: best so far)
#define BM 128
#define BN 128
#define BK 64
#define SA 72            // padded smem row stride (bf16): 144 B, 16B-aligned rows, ldmatrix conflict-free
#define NK (D_DIM / BK)  // 8
#define NSTAGE 3

#define A_SZ (BM * SA * 2)              // 18432 B per stage
#define STAGE (2 * BM * SA * 2)         // 36864 B per stage
#define RED_OFF (NSTAGE * STAGE)        // 110592
#define MBAR_OFF (RED_OFF + BM * 4)     // 111104 (8B-aligned)
#define SMEM_TOTAL (MBAR_OFF + 64)      // 111168 B -> 2 CTAs/SM (217 KB < 228 KB)

// Scratch (static device globals: allocation-free per harness rules).
__device__ __align__(16) __nv_bfloat16 g_Bn[(size_t)B_ROWS * D_DIM];
__device__ __align__(16) __nv_bfloat16 g_Pn[(size_t)C_COLS * D_DIM];
__device__ float g_rowacc[B_ROWS];
__device__ float g_pos[B_ROWS];

__device__ __forceinline__ uint32_t smem_u32(const void* p) {
    uint32_t a;
    asm("{ .reg .u64 t; cvta.to.shared.u64 t, %1; cvt.u32.u64 %0, t; }" : "=r"(a) : "l"(p));
    return a;
}
__device__ __forceinline__ void cp_async16(uint32_t sm, const void* gm) {
    asm volatile("cp.async.cg.shared.global [%0], [%1], 16;\n" ::"r"(sm), "l"(gm));
}
__device__ __forceinline__ void cp_async_arrive(uint32_t mbar) {
    asm volatile("cp.async.mbarrier.arrive.noinc.shared.b64 [%0];" ::"r"(mbar) : "memory");
}
__device__ __forceinline__ void mbar_init(uint32_t mbar, uint32_t cnt) {
    asm volatile("mbarrier.init.shared.b64 [%0], %1;" ::"r"(mbar), "r"(cnt) : "memory");
}
__device__ __forceinline__ void mbar_arrive(uint32_t mbar) {
    asm volatile("mbarrier.arrive.shared.b64 _, [%0];" ::"r"(mbar) : "memory");
}
__device__ __forceinline__ void mbar_wait(uint32_t mbar, uint32_t parity) {
    asm volatile(
        "{\n\t.reg .pred P1;\n\t"
        "W%=:\n\t"
        "mbarrier.try_wait.parity.acquire.cta.shared::cta.b64 P1, [%0], %1, 0x989680;\n\t"
        "@P1 bra.uni D%=;\n\t"
        "bra.uni W%=;\n\t"
        "D%=:\n\t}"
        ::"r"(mbar), "r"(parity) : "memory");
}
__device__ __forceinline__ void ldm_x4(uint32_t& r0, uint32_t& r1, uint32_t& r2, uint32_t& r3,
                                       uint32_t addr) {
    asm volatile("ldmatrix.sync.aligned.m8n8.x4.shared.b16 {%0,%1,%2,%3}, [%4];"
                 : "=r"(r0), "=r"(r1), "=r"(r2), "=r"(r3)
                 : "r"(addr));
}

// ---------------------------------------------------------------------------
// Normalize both tensors -> bf16 (norm 3); rows [0,1024) = embeddings,
// rows [1024, 1024+32768) = proxies. Also zero row accumulators.
// grid = 33792, block = 128
// ---------------------------------------------------------------------------
__global__ void k_norm(const float* __restrict__ emb, const float* __restrict__ pxy) {
    int row = blockIdx.x;
    int tid = threadIdx.x;
    const float* src;
    __nv_bfloat16* dstBase;
    if (row < B_ROWS) {
        src = emb + (size_t)row * D_DIM;
        dstBase = g_Bn + (size_t)row * D_DIM;
    } else {
        int pr = row - B_ROWS;
        src = pxy + (size_t)pr * D_DIM;
        dstBase = g_Pn + (size_t)pr * D_DIM;
    }
    float4 v = ((const float4*)src)[tid];
    float s = v.x * v.x + v.y * v.y + v.z * v.z + v.w * v.w;
#pragma unroll
    for (int o = 16; o > 0; o >>= 1) s += __shfl_xor_sync(0xffffffffu, s, o);
    __shared__ float ss[4];
    if ((tid & 31) == 0) ss[tid >> 5] = s;
    __syncthreads();
    float tot = ss[0] + ss[1] + ss[2] + ss[3];
    float scale = 3.0f / fmaxf(sqrtf(tot), 1e-12f);
    __nv_bfloat162 p0 = __floats2bfloat162_rn(v.x * scale, v.y * scale);
    __nv_bfloat162 p1 = __floats2bfloat162_rn(v.z * scale, v.w * scale);
    __nv_bfloat162* dst = (__nv_bfloat162*)(dstBase + tid * 4);
    dst[0] = p0;
    dst[1] = p1;
    if (row < B_ROWS && tid == 0) g_rowacc[row] = 0.0f;
}

// ---------------------------------------------------------------------------
// Positive distances with labels dtype autodetect (int32 vs int64 storage)
// ---------------------------------------------------------------------------
__global__ void k_pos(const int* __restrict__ lab32) {
    int row = blockIdx.x;
    int tid = threadIdx.x;
    int det = 0;
    for (int j = tid; j < 512; j += 128) det |= lab32[2 * j + 1];
#pragma unroll
    for (int o = 16; o > 0; o >>= 1) det |= __shfl_xor_sync(0xffffffffu, det, o);
    __shared__ int sOr[4];
    if ((tid & 31) == 0) sOr[tid >> 5] = det;
    __syncthreads();
    int is64 = ((sOr[0] | sOr[1] | sOr[2] | sOr[3]) == 0);
    int lab = is64 ? lab32[2 * row] : lab32[row];
    lab &= (C_COLS - 1);

    const __nv_bfloat162* a = (const __nv_bfloat162*)(g_Bn + (size_t)row * D_DIM);
    const __nv_bfloat162* b = (const __nv_bfloat162*)(g_Pn + (size_t)lab * D_DIM);
    float s = 0.0f;
#pragma unroll
    for (int j = 0; j < 2; j++) {
        int idx = tid * 2 + j;
        float2 fa = __bfloat1622float2(a[idx]);
        float2 fb = __bfloat1622float2(b[idx]);
        s += fa.x * fb.x + fa.y * fb.y;
    }
#pragma unroll
    for (int o = 16; o > 0; o >>= 1) s += __shfl_xor_sync(0xffffffffu, s, o);
    __shared__ float ss[4];
    if ((tid & 31) == 0) ss[tid >> 5] = s;
    __syncthreads();
    if (tid == 0) {
        float dot = ss[0] + ss[1] + ss[2] + ss[3];
        g_pos[row] = 18.0f - 2.0f * dot;
    }
}

// ---------------------------------------------------------------------------
// GEMM s = Bn @ Pn^T fused with exp(2s-18) row-sum epilogue.
// grid = (C/BN, B/BM) = (256, 8), block = 256 (8 warps, 2x4 warp grid).
// Warp tile 64x32 via m16n8k16 mma.sync; fragments via ldmatrix.x4.
// BK=64, 3-stage cp.async pipeline with mbarrier flow control (NO mainloop
// __syncthreads): full[s] (count 256, cp.async async-arrive) signals data
// ready; readdone[s] (count 256) gates stage reuse. Warps drift instead of
// restarting in lockstep, so ldmatrix bursts desynchronize.
//   stage s = kk%3, round u = kk/3, parity = u&1 for both barriers.
// ---------------------------------------------------------------------------
__global__ __launch_bounds__(256, 2) void k_gemm() {
    extern __shared__ __align__(16) char dsm[];
    float* red = (float*)(dsm + RED_OFF);

    int tid = threadIdx.x;
    int mBase = blockIdx.y * BM;
    int nBase = blockIdx.x * BN;
    int lane = tid & 31, warp = tid >> 5;
    int g = lane >> 2, t = lane & 3;
    int wm = (warp >> 2) * 64;  // 0 or 64
    int wn = (warp & 3) * 32;   // 0..96

    uint32_t sbase = smem_u32(dsm);
    uint32_t mbF = sbase + MBAR_OFF;       // full[0..2] at +0,+8,+16
    uint32_t mbR = sbase + MBAR_OFF + 24;  // readdone[0..2] at +24,+32,+40

    if (tid == 0) {
#pragma unroll
        for (int s = 0; s < NSTAGE; s++) {
            mbar_init(mbF + s * 8, 256);
            mbar_init(mbR + s * 8, 256);
        }
    }

    // ldmatrix per-lane address components (conflict-free with SA=72)
    int aR = (lane & 7) + ((lane >> 3) & 1) * 8;
    int aC = ((lane >> 4) & 1) * 8;
    int bR = (lane & 7) + ((lane >> 4) & 1) * 8;
    int bC = ((lane >> 3) & 1) * 8;

    float acc[4][4][4];
#pragma unroll
    for (int mt = 0; mt < 4; mt++)
#pragma unroll
        for (int nt = 0; nt < 4; nt++)
#pragma unroll
            for (int cc = 0; cc < 4; cc++) acc[mt][nt][cc] = 0.0f;

    int r = tid >> 3;        // 0..31
    int c8 = (tid & 7) * 8;  // 0..56 elems

    const __nv_bfloat16* gA0 = g_Bn + (size_t)mBase * D_DIM;
    const __nv_bfloat16* gB0 = g_Pn + (size_t)nBase * D_DIM;

    auto load_stage = [&](int kk) {
        uint32_t aB = sbase + (kk % NSTAGE) * STAGE;
        uint32_t bB = aB + A_SZ;
        int ko = kk * BK;
#pragma unroll
        for (int rr = r; rr < BM; rr += 32) {
            cp_async16(aB + (rr * SA + c8) * 2, gA0 + (size_t)rr * D_DIM + ko + c8);
            cp_async16(bB + (rr * SA + c8) * 2, gB0 + (size_t)rr * D_DIM + ko + c8);
        }
    };

    __syncthreads();  // mbarrier init visible before any arrive

    // prologue: fill all 3 stages
#pragma unroll
    for (int p = 0; p < NSTAGE; p++) {
        load_stage(p);
        cp_async_arrive(mbF + p * 8);
    }

    for (int kk = 0; kk < NK; kk++) {
        int s = kk % NSTAGE;
        uint32_t par = (uint32_t)((kk / NSTAGE) & 1);
        mbar_wait(mbF + s * 8, par);  // stage s data resident + visible (acquire)

        uint32_t aT = sbase + s * STAGE;
        uint32_t bT = aT + A_SZ;
#pragma unroll
        for (int ks = 0; ks < 4; ks++) {
            int kb = ks * 16;
            uint32_t A[4][4], Bf[4][2];
#pragma unroll
            for (int p = 0; p < 2; p++)
                ldm_x4(Bf[2 * p][0], Bf[2 * p][1], Bf[2 * p + 1][0], Bf[2 * p + 1][1],
                       bT + ((wn + p * 16 + bR) * SA + kb + bC) * 2);
#pragma unroll
            for (int mt = 0; mt < 4; mt++)
                ldm_x4(A[mt][0], A[mt][1], A[mt][2], A[mt][3],
                       aT + ((wm + mt * 16 + aR) * SA + kb + aC) * 2);
#pragma unroll
            for (int mt = 0; mt < 4; mt++)
#pragma unroll
                for (int nt = 0; nt < 4; nt++) {
                    asm volatile(
                        "mma.sync.aligned.m16n8k16.row.col.f32.bf16.bf16.f32 "
                        "{%0,%1,%2,%3}, {%4,%5,%6,%7}, {%8,%9}, {%0,%1,%2,%3};\n"
                        : "+f"(acc[mt][nt][0]), "+f"(acc[mt][nt][1]),
                          "+f"(acc[mt][nt][2]), "+f"(acc[mt][nt][3])
                        : "r"(A[mt][0]), "r"(A[mt][1]), "r"(A[mt][2]), "r"(A[mt][3]),
                          "r"(Bf[nt][0]), "r"(Bf[nt][1]));
                }
        }

        if (kk + NSTAGE < NK) {
            // signal done reading stage s, wait for ALL warps, then refill it
            mbar_arrive(mbR + s * 8);
            mbar_wait(mbR + s * 8, par);
            load_stage(kk + NSTAGE);
            cp_async_arrive(mbF + s * 8);
        }
    }

    // Epilogue: e = exp(2s - 18); per-row sums -> smem -> one global atomic/row
    __syncthreads();
    if (tid < BM) red[tid] = 0.0f;
    __syncthreads();

    float lsum[4][2];
#pragma unroll
    for (int mt = 0; mt < 4; mt++) { lsum[mt][0] = 0.0f; lsum[mt][1] = 0.0f; }
#pragma unroll
    for (int mt = 0; mt < 4; mt++)
#pragma unroll
        for (int nt = 0; nt < 4; nt++) {
            lsum[mt][0] += __expf(fmaf(2.0f, acc[mt][nt][0], -18.0f))
                         + __expf(fmaf(2.0f, acc[mt][nt][1], -18.0f));
            lsum[mt][1] += __expf(fmaf(2.0f, acc[mt][nt][2], -18.0f))
                         + __expf(fmaf(2.0f, acc[mt][nt][3], -18.0f));
        }
#pragma unroll
    for (int mt = 0; mt < 4; mt++)
#pragma unroll
        for (int h = 0; h < 2; h++) {
            float v = lsum[mt][h];
            v += __shfl_xor_sync(0xffffffffu, v, 1);
            v += __shfl_xor_sync(0xffffffffu, v, 2);
            if (t == 0) atomicAdd(&red[wm + mt * 16 + h * 8 + g], v);
        }
    __syncthreads();
    if (tid < BM) atomicAdd(&g_rowacc[mBase + tid], red[tid]);
}

// ---------------------------------------------------------------------------
// Finalize: loss_i = pos_dist_i + log(rowacc_i - exp(-pos_dist_i)); mean
// ---------------------------------------------------------------------------
__global__ void k_final(float* __restrict__ out) {
    int i = threadIdx.x;
    float pd = g_pos[i];
    float negsum = g_rowacc[i] - __expf(-pd);
    float v = pd + logf(negsum);
#pragma unroll
    for (int o = 16; o > 0; o >>= 1) v += __shfl_xor_sync(0xffffffffu, v, o);
    __shared__ float ss[32];
    if ((i & 31) == 0) ss[i >> 5] = v;
    __syncthreads();
    if (i < 32) {
        float w = ss[i];
#pragma unroll
        for (int o = 16; o > 0; o >>= 1) w += __shfl_xor_sync(0xffffffffu, w, o);
        if (i == 0) out[0] = w * (1.0f / (float)B_ROWS);
    }
}

// ---------------------------------------------------------------------------
extern "C" void kernel_launch(void* const* d_in, const int* in_sizes, int n_in,
                              void* d_out, int out_size) {
    (void)out_size;
    const float* emb = nullptr;
    const float* pxy = nullptr;
    const int* lab = nullptr;
    for (int i = 0; i < n_in; i++) {
        if (in_sizes[i] == B_ROWS * D_DIM) emb = (const float*)d_in[i];
        else if (in_sizes[i] == C_COLS * D_DIM) pxy = (const float*)d_in[i];
        else lab = (const int*)d_in[i];
    }
    float* out = (float*)d_out;

    static bool attr_done = false;
    if (!attr_done) {
        cudaFuncSetAttribute(k_gemm, cudaFuncAttributeMaxDynamicSharedMemorySize, SMEM_TOTAL);
        attr_done = true;
    }

    k_norm<<<B_ROWS + C_COLS, 128>>>(emb, pxy);
    k_pos<<<B_ROWS, 128>>>(lab);
    k_gemm<<<dim3(C_COLS / BN, B_ROWS / BM), 256, SMEM_TOTAL>>>();
    k_final<<<1, 1024>>>(out);
}

// round 15
// speedup vs baseline: 1.1327x; 1.0605x over previous
#include <cuda_runtime.h>
#include <cuda_bf16.h>
#include <cuda_fp16.h>
#include <cstdint>

// Problem shape (fixed by dataset)
#define B_ROWS 1024
#define C_COLS 32768
#define D_DIM  512

// FP8 GEMM tiling: CTA 128x128, 8 warps (2x4), warp tile 64x32, m16n8k32 e4m3
#define BM 128
#define BN 128
#define BK 128                 // fp8 elems per stage (= 128 B rows)
#define SAB 144                // smem row stride in BYTES (9x16B: ldmatrix conflict-free)
#define NK (D_DIM / BK)        // 4
#define NSTAGE 3

#define A_SZ (BM * SAB)                 // 18432 B per stage
#define STAGE (2 * BM * SAB)            // 36864 B per stage (A+B)
#define RED_OFF (NSTAGE * STAGE)        // 110592
#define SMEM_TOTAL (RED_OFF + BM * 4)   // 111104 B -> 2 CTAs/SM

// Scratch (static device globals: allocation-free per harness rules).
__device__ __align__(16) uint8_t g_Bn[(size_t)B_ROWS * D_DIM];   // e4m3
__device__ __align__(16) uint8_t g_Pn[(size_t)C_COLS * D_DIM];   // e4m3
__device__ float g_rowacc[B_ROWS];
__device__ float g_pos[B_ROWS];

__device__ __forceinline__ uint32_t smem_u32(const void* p) {
    uint32_t a;
    asm("{ .reg .u64 t; cvta.to.shared.u64 t, %1; cvt.u32.u64 %0, t; }" : "=r"(a) : "l"(p));
    return a;
}
__device__ __forceinline__ void cp_async16(uint32_t sm, const void* gm) {
    asm volatile("cp.async.cg.shared.global [%0], [%1], 16;\n" ::"r"(sm), "l"(gm));
}
__device__ __forceinline__ void ldm_x4(uint32_t& r0, uint32_t& r1, uint32_t& r2, uint32_t& r3,
                                       uint32_t addr) {
    asm volatile("ldmatrix.sync.aligned.m8n8.x4.shared.b16 {%0,%1,%2,%3}, [%4];"
                 : "=r"(r0), "=r"(r1), "=r"(r2), "=r"(r3)
                 : "r"(addr));
}
// pack 4 floats -> 4 e4m3 bytes (byte i = x_i)
__device__ __forceinline__ uint32_t pack4_e4m3(float x0, float x1, float x2, float x3) {
    uint16_t lo, hi;
    asm("cvt.rn.satfinite.e4m3x2.f32 %0, %1, %2;" : "=h"(lo) : "f"(x1), "f"(x0));
    asm("cvt.rn.satfinite.e4m3x2.f32 %0, %1, %2;" : "=h"(hi) : "f"(x3), "f"(x2));
    return (uint32_t)lo | ((uint32_t)hi << 16);
}
// unpack 2 e4m3 -> float2 (exact via f16)
__device__ __forceinline__ float2 unpack2_e4m3(uint16_t v) {
    uint32_t h2;
    asm("cvt.rn.f16x2.e4m3x2 %0, %1;" : "=r"(h2) : "h"(v));
    __half2 h = *reinterpret_cast<__half2*>(&h2);
    return __half22float2(h);
}

// ---------------------------------------------------------------------------
// Normalize both tensors -> e4m3 (norm 3); rows [0,1024) = embeddings,
// rows [1024,1024+32768) = proxies. Zero row accumulators.
// grid = 33792, block = 128
// ---------------------------------------------------------------------------
__global__ void k_norm(const float* __restrict__ emb, const float* __restrict__ pxy) {
    int row = blockIdx.x;
    int tid = threadIdx.x;
    const float* src;
    uint8_t* dstBase;
    if (row < B_ROWS) {
        src = emb + (size_t)row * D_DIM;
        dstBase = g_Bn + (size_t)row * D_DIM;
    } else {
        int pr = row - B_ROWS;
        src = pxy + (size_t)pr * D_DIM;
        dstBase = g_Pn + (size_t)pr * D_DIM;
    }
    float4 v = ((const float4*)src)[tid];
    float s = v.x * v.x + v.y * v.y + v.z * v.z + v.w * v.w;
#pragma unroll
    for (int o = 16; o > 0; o >>= 1) s += __shfl_xor_sync(0xffffffffu, s, o);
    __shared__ float ss[4];
    if ((tid & 31) == 0) ss[tid >> 5] = s;
    __syncthreads();
    float tot = ss[0] + ss[1] + ss[2] + ss[3];
    float scale = 3.0f / fmaxf(sqrtf(tot), 1e-12f);
    uint32_t packed = pack4_e4m3(v.x * scale, v.y * scale, v.z * scale, v.w * scale);
    *(uint32_t*)(dstBase + tid * 4) = packed;
    if (row < B_ROWS && tid == 0) g_rowacc[row] = 0.0f;
}

// ---------------------------------------------------------------------------
// Positive distances with labels dtype autodetect (int32 vs int64 storage)
// ---------------------------------------------------------------------------
__global__ void k_pos(const int* __restrict__ lab32) {
    int row = blockIdx.x;
    int tid = threadIdx.x;
    int det = 0;
    for (int j = tid; j < 512; j += 128) det |= lab32[2 * j + 1];
#pragma unroll
    for (int o = 16; o > 0; o >>= 1) det |= __shfl_xor_sync(0xffffffffu, det, o);
    __shared__ int sOr[4];
    if ((tid & 31) == 0) sOr[tid >> 5] = det;
    __syncthreads();
    int is64 = ((sOr[0] | sOr[1] | sOr[2] | sOr[3]) == 0);
    int lab = is64 ? lab32[2 * row] : lab32[row];
    lab &= (C_COLS - 1);

    uint32_t av = *(const uint32_t*)(g_Bn + (size_t)row * D_DIM + tid * 4);
    uint32_t bv = *(const uint32_t*)(g_Pn + (size_t)lab * D_DIM + tid * 4);
    float2 a0 = unpack2_e4m3((uint16_t)(av & 0xffff));
    float2 a1 = unpack2_e4m3((uint16_t)(av >> 16));
    float2 b0 = unpack2_e4m3((uint16_t)(bv & 0xffff));
    float2 b1 = unpack2_e4m3((uint16_t)(bv >> 16));
    float s = a0.x * b0.x + a0.y * b0.y + a1.x * b1.x + a1.y * b1.y;
#pragma unroll
    for (int o = 16; o > 0; o >>= 1) s += __shfl_xor_sync(0xffffffffu, s, o);
    __shared__ float ss[4];
    if ((tid & 31) == 0) ss[tid >> 5] = s;
    __syncthreads();
    if (tid == 0) {
        float dot = ss[0] + ss[1] + ss[2] + ss[3];
        g_pos[row] = 18.0f - 2.0f * dot;
    }
}

// ---------------------------------------------------------------------------
// FP8 GEMM s = Bn @ Pn^T fused with exp(2s-18) row-sum epilogue.
// grid = (C/BN, B/BM) = (256, 8), block = 256.
// mma.sync.m16n8k32.e4m3: fragment layout is byte-identical to bf16 k16,
// so ldmatrix addressing (in bytes) is unchanged from the validated R12 code.
// BK=128 fp8 -> only 4 k-iterations; 3-stage cp.async, one barrier per iter.
// ---------------------------------------------------------------------------
__global__ __launch_bounds__(256, 2) void k_gemm() {
    extern __shared__ __align__(16) char dsm[];
    float* red = (float*)(dsm + RED_OFF);

    int tid = threadIdx.x;
    int mBase = blockIdx.y * BM;
    int nBase = blockIdx.x * BN;
    int lane = tid & 31, warp = tid >> 5;
    int g = lane >> 2, t = lane & 3;
    int wm = (warp >> 2) * 64;  // 0 or 64
    int wn = (warp & 3) * 32;   // 0..96

    uint32_t sbase = smem_u32(dsm);

    // ldmatrix per-lane components (bytes; conflict-free with 144 B stride)
    int aR = (lane & 7) + ((lane >> 3) & 1) * 8;
    int aC = ((lane >> 4) & 1) * 16;  // 16 B = 16 fp8
    int bR = (lane & 7) + ((lane >> 4) & 1) * 8;
    int bC = ((lane >> 3) & 1) * 16;

    float acc[4][4][4];
#pragma unroll
    for (int mt = 0; mt < 4; mt++)
#pragma unroll
        for (int nt = 0; nt < 4; nt++)
#pragma unroll
            for (int cc = 0; cc < 4; cc++) acc[mt][nt][cc] = 0.0f;

    int r = tid >> 3;          // 0..31
    int cB = (tid & 7) * 16;   // byte offset in 128 B row

    const uint8_t* gA0 = g_Bn + (size_t)mBase * D_DIM;
    const uint8_t* gB0 = g_Pn + (size_t)nBase * D_DIM;

    auto load_stage = [&](int kk) {
        uint32_t aB = sbase + (kk % NSTAGE) * STAGE;
        uint32_t bB = aB + A_SZ;
        int ko = kk * BK;  // bytes == elems
#pragma unroll
        for (int rr = r; rr < BM; rr += 32) {
            cp_async16(aB + rr * SAB + cB, gA0 + (size_t)rr * D_DIM + ko + cB);
            cp_async16(bB + rr * SAB + cB, gB0 + (size_t)rr * D_DIM + ko + cB);
        }
    };

    load_stage(0);
    asm volatile("cp.async.commit_group;\n");
    load_stage(1);
    asm volatile("cp.async.commit_group;\n");

    for (int kk = 0; kk < NK; kk++) {
        asm volatile("cp.async.wait_group 1;\n");  // stage kk resident
        __syncthreads();                           // visible; iter kk-1 reads done

        if (kk + 2 < NK) load_stage(kk + 2);       // overwrites stage read at kk-1
        asm volatile("cp.async.commit_group;\n");

        uint32_t aT = sbase + (kk % NSTAGE) * STAGE;
        uint32_t bT = aT + A_SZ;
#pragma unroll
        for (int ks = 0; ks < 4; ks++) {
            int kb = ks * 32;  // 32 fp8 bytes per k-step
            uint32_t A[4][4], Bf[4][2];
#pragma unroll
            for (int p = 0; p < 2; p++)
                ldm_x4(Bf[2 * p][0], Bf[2 * p][1], Bf[2 * p + 1][0], Bf[2 * p + 1][1],
                       bT + (wn + p * 16 + bR) * SAB + kb + bC);
#pragma unroll
            for (int mt = 0; mt < 4; mt++)
                ldm_x4(A[mt][0], A[mt][1], A[mt][2], A[mt][3],
                       aT + (wm + mt * 16 + aR) * SAB + kb + aC);
#pragma unroll
            for (int mt = 0; mt < 4; mt++)
#pragma unroll
                for (int nt = 0; nt < 4; nt++) {
                    asm volatile(
                        "mma.sync.aligned.m16n8k32.row.col.f32.e4m3.e4m3.f32 "
                        "{%0,%1,%2,%3}, {%4,%5,%6,%7}, {%8,%9}, {%0,%1,%2,%3};\n"
                        : "+f"(acc[mt][nt][0]), "+f"(acc[mt][nt][1]),
                          "+f"(acc[mt][nt][2]), "+f"(acc[mt][nt][3])
                        : "r"(A[mt][0]), "r"(A[mt][1]), "r"(A[mt][2]), "r"(A[mt][3]),
                          "r"(Bf[nt][0]), "r"(Bf[nt][1]));
                }
        }
    }

    // Epilogue: e = exp(2s - 18); per-row sums -> smem -> one global atomic/row
    __syncthreads();
    if (tid < BM) red[tid] = 0.0f;
    __syncthreads();

    float lsum[4][2];
#pragma unroll
    for (int mt = 0; mt < 4; mt++) { lsum[mt][0] = 0.0f; lsum[mt][1] = 0.0f; }
#pragma unroll
    for (int mt = 0; mt < 4; mt++)
#pragma unroll
        for (int nt = 0; nt < 4; nt++) {
            lsum[mt][0] += __expf(fmaf(2.0f, acc[mt][nt][0], -18.0f))
                         + __expf(fmaf(2.0f, acc[mt][nt][1], -18.0f));
            lsum[mt][1] += __expf(fmaf(2.0f, acc[mt][nt][2], -18.0f))
                         + __expf(fmaf(2.0f, acc[mt][nt][3], -18.0f));
        }
#pragma unroll
    for (int mt = 0; mt < 4; mt++)
#pragma unroll
        for (int h = 0; h < 2; h++) {
            float v = lsum[mt][h];
            v += __shfl_xor_sync(0xffffffffu, v, 1);
            v += __shfl_xor_sync(0xffffffffu, v, 2);
            if (t == 0) atomicAdd(&red[wm + mt * 16 + h * 8 + g], v);
        }
    __syncthreads();
    if (tid < BM) atomicAdd(&g_rowacc[mBase + tid], red[tid]);
}

// ---------------------------------------------------------------------------
// Finalize: loss_i = pos_dist_i + log(rowacc_i - exp(-pos_dist_i)); mean
// ---------------------------------------------------------------------------
__global__ void k_final(float* __restrict__ out) {
    int i = threadIdx.x;
    float pd = g_pos[i];
    float negsum = g_rowacc[i] - __expf(-pd);
    float v = pd + logf(negsum);
#pragma unroll
    for (int o = 16; o > 0; o >>= 1) v += __shfl_xor_sync(0xffffffffu, v, o);
    __shared__ float ss[32];
    if ((i & 31) == 0) ss[i >> 5] = v;
    __syncthreads();
    if (i < 32) {
        float w = ss[i];
#pragma unroll
        for (int o = 16; o > 0; o >>= 1) w += __shfl_xor_sync(0xffffffffu, w, o);
        if (i == 0) out[0] = w * (1.0f / (float)B_ROWS);
    }
}

// ---------------------------------------------------------------------------
extern "C" void kernel_launch(void* const* d_in, const int* in_sizes, int n_in,
                              void* d_out, int out_size) {
    (void)out_size;
    const float* emb = nullptr;
    const float* pxy = nullptr;
    const int* lab = nullptr;
    for (int i = 0; i < n_in; i++) {
        if (in_sizes[i] == B_ROWS * D_DIM) emb = (const float*)d_in[i];
        else if (in_sizes[i] == C_COLS * D_DIM) pxy = (const float*)d_in[i];
        else lab = (const int*)d_in[i];
    }
    float* out = (float*)d_out;

    static bool attr_done = false;
    if (!attr_done) {
        cudaFuncSetAttribute(k_gemm, cudaFuncAttributeMaxDynamicSharedMemorySize, SMEM_TOTAL);
        attr_done = true;
    }

    k_norm<<<B_ROWS + C_COLS, 128>>>(emb, pxy);
    k_pos<<<B_ROWS, 128>>>(lab);
    k_gemm<<<dim3(C_COLS / BN, B_ROWS / BM), 256, SMEM_TOTAL>>>();
    k_final<<<1, 1024>>>(out);
}